// round 15
// baseline (speedup 1.0000x reference)
#include <cuda_runtime.h>
#include <cuda_bf16.h>
#include <cstdint>

#define NB   1024
#define NS1  25
#define NS2  10
#define DF   128
#define ROWS1 (NB * NS1)   // 25600
#define MEGA_BLOCKS (2 * (ROWS1 / 64))   // 800
#define TAIL_SLICES 32

// ---------------- scratch (no allocations allowed) ----------------
__device__ float g_X0[(size_t)NB * 256];
__device__ float g_Y0[(size_t)NB * 256];
__device__ float g_M1[(size_t)NB * 256];     // accumulated mean over s1 (atomic)
__device__ int   g_ctr;                      // mega finish tickets (zeroed by prep)
// W^T bf16 hi/lo: [ws0: 128n x 128k @0][wn0: @16384][ws1: 128n x 256k @32768][wn1: @65536]
__device__ __align__(16) __nv_bfloat16 g_WtH[98304];
__device__ __align__(16) __nv_bfloat16 g_WtL[98304];

// ---------------- helpers ----------------
__device__ __forceinline__ void split4(const float4& v, uint2& hi, uint2& lo) {
    float vv[4] = {v.x, v.y, v.z, v.w};
    uint32_t hp[2], lp[2];
#pragma unroll
    for (int q = 0; q < 2; q++) {
        __nv_bfloat16 h0 = __float2bfloat16(vv[2 * q]);
        __nv_bfloat16 h1 = __float2bfloat16(vv[2 * q + 1]);
        __nv_bfloat16 l0 = __float2bfloat16(vv[2 * q] - __bfloat162float(h0));
        __nv_bfloat16 l1 = __float2bfloat16(vv[2 * q + 1] - __bfloat162float(h1));
        hp[q] = ((uint32_t)__bfloat16_as_ushort(h1) << 16) | __bfloat16_as_ushort(h0);
        lp[q] = ((uint32_t)__bfloat16_as_ushort(l1) << 16) | __bfloat16_as_ushort(l0);
    }
    hi = make_uint2(hp[0], hp[1]);
    lo = make_uint2(lp[0], lp[1]);
}
__device__ __forceinline__ uint32_t smem_to_u32(const void* p) {
    uint32_t a;
    asm("{ .reg .u64 t; cvta.to.shared.u64 t, %1; cvt.u32.u64 %0, t; }"
        : "=r"(a) : "l"(p));
    return a;
}
#define CP_ASYNC16(dst_u32, src_ptr) \
    asm volatile("cp.async.cg.shared.global [%0], [%1], 16;" \
        :: "r"(dst_u32), "l"(src_ptr) : "memory")
#define CP_ASYNC_WAIT_ALL() \
    asm volatile("cp.async.commit_group;\ncp.async.wait_group 0;" ::: "memory")

__device__ __forceinline__ void mma16816(float* c, const uint32_t* a, const uint32_t* b) {
    asm volatile(
        "mma.sync.aligned.m16n8k16.row.col.f32.bf16.bf16.f32 "
        "{%0,%1,%2,%3}, {%4,%5,%6,%7}, {%8,%9}, {%0,%1,%2,%3};"
        : "+f"(c[0]), "+f"(c[1]), "+f"(c[2]), "+f"(c[3])
        : "r"(a[0]), "r"(a[1]), "r"(a[2]), "r"(a[3]), "r"(b[0]), "r"(b[1]));
}
__device__ __forceinline__ void f4add(float4& a, const float4& b) {
    a.x += b.x; a.y += b.y; a.z += b.z; a.w += b.w;
}
__device__ __forceinline__ float4 ldcs4(const float* p) {
    return __ldcs((const float4*)p);
}
__device__ __forceinline__ float4 ldcg4(const float* p) {
    return __ldcg((const float4*)p);
}

// ---------------- prep: weights; blocks >=96 zero M1; zero ctr ----------------
__global__ void prep_w_kernel(const float* __restrict__ w0s, const float* __restrict__ w0n,
                              const float* __restrict__ w1s, const float* __restrict__ w1n) {
    int b = blockIdx.x;
    if (b >= 96) {
        if (b == 96 && threadIdx.x == 0) g_ctr = 0;
        int u = (b - 96) * 256 + threadIdx.x;     // 64 blocks * 256 = 16384 threads
        for (int i = u; i < 65536; i += 16384)
            ((float4*)g_M1)[i] = make_float4(0.f, 0.f, 0.f, 0.f);
        return;
    }
    __shared__ float t[32][33];
    const float* W; int K, off, tile;
    if (b < 16)      { W = w0s; K = 128; off = 0;     tile = b; }
    else if (b < 32) { W = w0n; K = 128; off = 16384; tile = b - 16; }
    else if (b < 64) { W = w1s; K = 256; off = 32768; tile = b - 32; }
    else             { W = w1n; K = 256; off = 65536; tile = b - 64; }
    int tr = (tile >> 2) * 32;
    int tc = (tile & 3) * 32;
    int tx = threadIdx.x & 31, ty = threadIdx.x >> 5;
#pragma unroll
    for (int p = 0; p < 32; p += 8)
        t[ty + p][tx] = W[(size_t)(tr + ty + p) * 128 + tc + tx];
    __syncthreads();
#pragma unroll
    for (int p = 0; p < 32; p += 8) {
        int n = tc + ty + p, k = tr + tx;
        float v = t[tx][ty + p];
        __nv_bfloat16 h = __float2bfloat16(v);
        __nv_bfloat16 l = __float2bfloat16(v - __bfloat162float(h));
        size_t o = (size_t)off + (size_t)n * K + k;
        g_WtH[o] = h;
        g_WtL[o] = l;
    }
}

// ---------------- gather0: X0 = [h0 | mean_S1(h1)], MLP-batched ----------------
__global__ void gather0_kernel(const float* __restrict__ feat,
                               const int* __restrict__ s0,
                               const int* __restrict__ s1) {
    int warp = (blockIdx.x * blockDim.x + threadIdx.x) >> 5;
    int lane = threadIdx.x & 31;
    if (warp >= NB) return;
    int c = lane * 4;

    long iself = s0[warp];
    *(float4*)(g_X0 + (size_t)warp * 256 + c) =
        *(const float4*)(feat + iself * DF + c);

    const int* p = s1 + (size_t)warp * NS1;
    int idxs[NS1];
#pragma unroll
    for (int j = 0; j < NS1; j++) idxs[j] = p[j];

    float4 acc = make_float4(0.f, 0.f, 0.f, 0.f);
#pragma unroll
    for (int base = 0; base < 25; base += 5) {
        float4 v[5];
#pragma unroll
        for (int j = 0; j < 5; j++)
            v[j] = *(const float4*)(feat + (long)idxs[base + j] * DF + c);
        f4add(v[0], v[1]); f4add(v[2], v[3]); f4add(v[0], v[2]);
        f4add(v[0], v[4]); f4add(acc, v[0]);
    }
    const float s = 1.0f / NS1;
    acc.x *= s; acc.y *= s; acc.z *= s; acc.w *= s;
    *(float4*)(g_X0 + (size_t)warp * 256 + 128 + c) = acc;
}

#define PADB 272   // smem row pitch in bytes

// ---------------- tail slice (device fn): out[row0:+64, 128+n0:+64] = relu(M1@Wn1) ----------------
__device__ void tail_slice(char* sb, int row0, int n0, float* __restrict__ out) {
    const uint32_t OFF_AH = 0;
    const uint32_t OFF_AL = 64 * PADB;
    const uint32_t OFF_BH = 2 * 64 * PADB;
    const uint32_t OFF_BL = 3 * 64 * PADB;
    const uint32_t smb = smem_to_u32(sb);
    const int tid = threadIdx.x;
    const int wid = tid >> 5;
    const int lane = tid & 31;
    const int g = lane >> 2;
    const int tg = lane & 3;
    const int wr = (wid >> 1) * 16;
    const int wc = (wid & 1) * 32;

    float acc[4][4];
#pragma unroll
    for (int j = 0; j < 4; j++)
#pragma unroll
        for (int q = 0; q < 4; q++) acc[j][q] = 0.f;

    for (int kc = 0; kc < 2; kc++) {
        const int koff = kc * 128;
        for (int idx = tid; idx < 1024; idx += 256) {
            int n = idx >> 4;
            int ch = (idx & 15) * 16;
            size_t gsrc = 65536 + (size_t)(n0 + n) * 256 + koff;
            uint32_t dst = n * PADB + ch;
            CP_ASYNC16(smb + OFF_BH + dst, (const char*)(g_WtH + gsrc) + ch);
            CP_ASYNC16(smb + OFF_BL + dst, (const char*)(g_WtL + gsrc) + ch);
        }
        for (int idx = tid; idx < 2048; idx += 256) {
            int r = idx >> 5;
            int cc4 = (idx & 31) * 4;
            float4 v = ldcg4(g_M1 + (size_t)(row0 + r) * 256 + koff + cc4);
            uint2 h, l;
            split4(v, h, l);
            *(uint2*)(sb + OFF_AH + r * PADB + cc4 * 2) = h;
            *(uint2*)(sb + OFF_AL + r * PADB + cc4 * 2) = l;
        }
        CP_ASYNC_WAIT_ALL();
        __syncthreads();

        const char* Ah = sb + OFF_AH;
        const char* Al = sb + OFF_AL;
        const char* Bh = sb + OFF_BH;
        const char* Bl = sb + OFF_BL;

#pragma unroll
        for (int ks = 0; ks < 8; ks++) {
            const int kb = (ks * 16 + tg * 2) * 2;
            uint32_t ah[4], al[4], bh[4][2], bl[4][2];
            int r = wr + g;
            ah[0] = *(const uint32_t*)(Ah + r * PADB + kb);
            ah[1] = *(const uint32_t*)(Ah + (r + 8) * PADB + kb);
            ah[2] = *(const uint32_t*)(Ah + r * PADB + kb + 16);
            ah[3] = *(const uint32_t*)(Ah + (r + 8) * PADB + kb + 16);
            al[0] = *(const uint32_t*)(Al + r * PADB + kb);
            al[1] = *(const uint32_t*)(Al + (r + 8) * PADB + kb);
            al[2] = *(const uint32_t*)(Al + r * PADB + kb + 16);
            al[3] = *(const uint32_t*)(Al + (r + 8) * PADB + kb + 16);
#pragma unroll
            for (int j = 0; j < 4; j++) {
                int n = wc + j * 8 + g;
                bh[j][0] = *(const uint32_t*)(Bh + n * PADB + kb);
                bh[j][1] = *(const uint32_t*)(Bh + n * PADB + kb + 16);
                bl[j][0] = *(const uint32_t*)(Bl + n * PADB + kb);
                bl[j][1] = *(const uint32_t*)(Bl + n * PADB + kb + 16);
            }
#pragma unroll
            for (int j = 0; j < 4; j++) {
                mma16816(acc[j], ah, bh[j]);
                mma16816(acc[j], al, bh[j]);
                mma16816(acc[j], ah, bl[j]);
            }
        }
        __syncthreads();
    }

    const int colg = 128 + n0 + wc;
    int r = row0 + wr + g;
#pragma unroll
    for (int j = 0; j < 4; j++) {
        int cgl = colg + j * 8 + tg * 2;
        float2 o0, o1;
        o0.x = fmaxf(acc[j][0], 0.f);
        o0.y = fmaxf(acc[j][1], 0.f);
        o1.x = fmaxf(acc[j][2], 0.f);
        o1.y = fmaxf(acc[j][3], 0.f);
        *(float2*)(out + (size_t)r * 256 + cgl) = o0;
        *(float2*)(out + (size_t)(r + 8) * 256 + cgl) = o1;
    }
}

// ---------------- mega: fused gather + HMMA bf16x3 + atomic mean + in-kernel tail ----------------
__global__ __launch_bounds__(256, 2)
void mega_kernel(const float* __restrict__ feat,
                 const int* __restrict__ s1,
                 const int* __restrict__ s2,
                 float* __restrict__ out) {
    const int tid = threadIdx.x;
    const int wid = tid >> 5;
    const int lane = tid & 31;
    const int c = lane * 4;

    extern __shared__ char sb[];
    __shared__ int s_ticket;
    const uint32_t OFF_AH = 0;
    const uint32_t OFF_AL = 64 * PADB;
    const uint32_t OFF_BH = 2 * 64 * PADB;
    const uint32_t OFF_BL = OFF_BH + 128 * PADB;
    const uint32_t smb = smem_to_u32(sb);

    const int half = blockIdx.x & 1;
    const int row0 = (blockIdx.x >> 1) * 64;

    for (int idx = tid; idx < 2048; idx += 256) {
        int n = idx >> 4;
        int ch = (idx & 15) * 16;
        size_t gsrc = (size_t)half * 16384 + (size_t)n * 128;
        uint32_t dst = n * PADB + ch;
        CP_ASYNC16(smb + OFF_BH + dst, (const char*)(g_WtH + gsrc) + ch);
        CP_ASYNC16(smb + OFF_BL + dst, (const char*)(g_WtL + gsrc) + ch);
    }

    if (half == 0) {
        long idxs[8];
#pragma unroll
        for (int it = 0; it < 8; it++) idxs[it] = s1[row0 + wid + it * 8];
        float4 v[8];
#pragma unroll
        for (int it = 0; it < 8; it++)
            v[it] = *(const float4*)(feat + idxs[it] * DF + c);
#pragma unroll
        for (int it = 0; it < 8; it++) {
            const int r = wid + it * 8;
            uint2 h, l;
            split4(v[it], h, l);
            *(uint2*)(sb + OFF_AH + r * PADB + lane * 8) = h;
            *(uint2*)(sb + OFF_AL + r * PADB + lane * 8) = l;
        }
    } else {
#pragma unroll
        for (int it = 0; it < 8; it++) {
            const int r = wid + it * 8;
            const int gr = row0 + r;
            const int* p = s2 + (size_t)gr * NS2;
            int idxs[NS2];
#pragma unroll
            for (int j = 0; j < NS2; j++) idxs[j] = p[j];
            float4 v[NS2];
#pragma unroll
            for (int j = 0; j < NS2; j++)
                v[j] = ldcs4(feat + (long)idxs[j] * DF + c);
            f4add(v[0], v[1]); f4add(v[2], v[3]); f4add(v[4], v[5]);
            f4add(v[6], v[7]); f4add(v[8], v[9]);
            f4add(v[0], v[2]); f4add(v[4], v[6]);
            f4add(v[0], v[4]); f4add(v[0], v[8]);
            const float s = 1.0f / NS2;
            v[0].x *= s; v[0].y *= s; v[0].z *= s; v[0].w *= s;
            uint2 h, l;
            split4(v[0], h, l);
            *(uint2*)(sb + OFF_AH + r * PADB + lane * 8) = h;
            *(uint2*)(sb + OFF_AL + r * PADB + lane * 8) = l;
        }
    }
    CP_ASYNC_WAIT_ALL();
    __syncthreads();

    {
        const char* Ah = sb + OFF_AH;
        const char* Al = sb + OFF_AL;
        const char* Bh = sb + OFF_BH;
        const char* Bl = sb + OFF_BL;

        const int g = lane >> 2;
        const int tg = lane & 3;
        const int wr = (wid >> 2) * 32;
        const int wc = (wid & 3) * 32;

        float acc[2][4][4];
#pragma unroll
        for (int i = 0; i < 2; i++)
#pragma unroll
            for (int j = 0; j < 4; j++)
#pragma unroll
                for (int q = 0; q < 4; q++) acc[i][j][q] = 0.f;

#pragma unroll
        for (int ks = 0; ks < 8; ks++) {
            const int kb = (ks * 16 + tg * 2) * 2;
            uint32_t ah[2][4], al[2][4], bh[4][2], bl[4][2];
#pragma unroll
            for (int i = 0; i < 2; i++) {
                int r = wr + i * 16 + g;
                ah[i][0] = *(const uint32_t*)(Ah + r * PADB + kb);
                ah[i][1] = *(const uint32_t*)(Ah + (r + 8) * PADB + kb);
                ah[i][2] = *(const uint32_t*)(Ah + r * PADB + kb + 16);
                ah[i][3] = *(const uint32_t*)(Ah + (r + 8) * PADB + kb + 16);
                al[i][0] = *(const uint32_t*)(Al + r * PADB + kb);
                al[i][1] = *(const uint32_t*)(Al + (r + 8) * PADB + kb);
                al[i][2] = *(const uint32_t*)(Al + r * PADB + kb + 16);
                al[i][3] = *(const uint32_t*)(Al + (r + 8) * PADB + kb + 16);
            }
#pragma unroll
            for (int j = 0; j < 4; j++) {
                int n = wc + j * 8 + g;
                bh[j][0] = *(const uint32_t*)(Bh + n * PADB + kb);
                bh[j][1] = *(const uint32_t*)(Bh + n * PADB + kb + 16);
                bl[j][0] = *(const uint32_t*)(Bl + n * PADB + kb);
                bl[j][1] = *(const uint32_t*)(Bl + n * PADB + kb + 16);
            }
#pragma unroll
            for (int i = 0; i < 2; i++)
#pragma unroll
                for (int j = 0; j < 4; j++) {
                    mma16816(acc[i][j], ah[i], bh[j]);
                    mma16816(acc[i][j], al[i], bh[j]);
                    mma16816(acc[i][j], ah[i], bl[j]);
                }
        }

        const int colg = half * 128 + wc;
        const float inv25 = 1.0f / NS1;
#pragma unroll
        for (int i = 0; i < 2; i++) {
            int r0g = row0 + wr + i * 16 + g;
            int b0 = r0g / NS1;
            int b1 = (r0g + 8) / NS1;
#pragma unroll
            for (int j = 0; j < 4; j++) {
                int cgl = colg + j * 8 + tg * 2;
                atomicAdd(&g_M1[(size_t)b0 * 256 + cgl],     fmaxf(acc[i][j][0], 0.f) * inv25);
                atomicAdd(&g_M1[(size_t)b0 * 256 + cgl + 1], fmaxf(acc[i][j][1], 0.f) * inv25);
                atomicAdd(&g_M1[(size_t)b1 * 256 + cgl],     fmaxf(acc[i][j][2], 0.f) * inv25);
                atomicAdd(&g_M1[(size_t)b1 * 256 + cgl + 1], fmaxf(acc[i][j][3], 0.f) * inv25);
            }
        }
    }

    // ---- finish ticket: last TAIL_SLICES CTAs compute the tail in the straggler shadow ----
    __syncthreads();
    if (tid == 0) {
        __threadfence();
        s_ticket = atomicAdd(&g_ctr, 1);
    }
    __syncthreads();
    int ticket = s_ticket;
    if (ticket < MEGA_BLOCKS - TAIL_SLICES) return;

    if (tid == 0) {
        while (*(volatile int*)&g_ctr < MEGA_BLOCKS) { }
        __threadfence();
    }
    __syncthreads();

    int slice = ticket - (MEGA_BLOCKS - TAIL_SLICES);   // 0..31
    tail_slice(sb, (slice & 15) * 64, (slice >> 4) * 64, out);
}

// ---------------- small HMMA GEMM (64x128 tiles) ----------------
__global__ __launch_bounds__(256, 2)
void small_hmma_kernel(const float* __restrict__ A0, const float* __restrict__ A1,
                       int acolmul, int woffbase, int woffstep, int kstride,
                       int kc_count, int colbase, float* __restrict__ out) {
    extern __shared__ char sb[];
    const uint32_t OFF_AH = 0;
    const uint32_t OFF_AL = 64 * PADB;
    const uint32_t OFF_BH = 2 * 64 * PADB;
    const uint32_t OFF_BL = OFF_BH + 128 * PADB;
    const uint32_t smb = smem_to_u32(sb);

    const int half = blockIdx.y;
    const int row0 = blockIdx.x * 64;
    const int tid = threadIdx.x;
    const int wid = tid >> 5;
    const int lane = tid & 31;
    const float* A = half ? A1 : A0;
    const int acol0 = acolmul * half;
    const int woff = woffbase + half * woffstep;

    const int g = lane >> 2;
    const int tg = lane & 3;
    const int wr = (wid >> 2) * 32;
    const int wc = (wid & 3) * 32;

    float acc[2][4][4];
#pragma unroll
    for (int i = 0; i < 2; i++)
#pragma unroll
        for (int j = 0; j < 4; j++)
#pragma unroll
            for (int q = 0; q < 4; q++) acc[i][j][q] = 0.f;

    for (int kc = 0; kc < kc_count; kc++) {
        const int koff = kc * 128;
        for (int idx = tid; idx < 2048; idx += 256) {
            int n = idx >> 4;
            int ch = (idx & 15) * 16;
            size_t gsrc = (size_t)woff + (size_t)n * kstride + koff;
            uint32_t dst = n * PADB + ch;
            CP_ASYNC16(smb + OFF_BH + dst, (const char*)(g_WtH + gsrc) + ch);
            CP_ASYNC16(smb + OFF_BL + dst, (const char*)(g_WtL + gsrc) + ch);
        }
        for (int idx = tid; idx < 2048; idx += 256) {
            int r = idx >> 5;
            int cc4 = (idx & 31) * 4;
            float4 v = *(const float4*)(A + (size_t)(row0 + r) * 256 + acol0 + koff + cc4);
            uint2 h, l;
            split4(v, h, l);
            *(uint2*)(sb + OFF_AH + r * PADB + cc4 * 2) = h;
            *(uint2*)(sb + OFF_AL + r * PADB + cc4 * 2) = l;
        }
        CP_ASYNC_WAIT_ALL();
        __syncthreads();

        const char* Ah = sb + OFF_AH;
        const char* Al = sb + OFF_AL;
        const char* Bh = sb + OFF_BH;
        const char* Bl = sb + OFF_BL;

#pragma unroll
        for (int ks = 0; ks < 8; ks++) {
            const int kb = (ks * 16 + tg * 2) * 2;
            uint32_t ah[2][4], al[2][4], bh[4][2], bl[4][2];
#pragma unroll
            for (int i = 0; i < 2; i++) {
                int r = wr + i * 16 + g;
                ah[i][0] = *(const uint32_t*)(Ah + r * PADB + kb);
                ah[i][1] = *(const uint32_t*)(Ah + (r + 8) * PADB + kb);
                ah[i][2] = *(const uint32_t*)(Ah + r * PADB + kb + 16);
                ah[i][3] = *(const uint32_t*)(Ah + (r + 8) * PADB + kb + 16);
                al[i][0] = *(const uint32_t*)(Al + r * PADB + kb);
                al[i][1] = *(const uint32_t*)(Al + (r + 8) * PADB + kb);
                al[i][2] = *(const uint32_t*)(Al + r * PADB + kb + 16);
                al[i][3] = *(const uint32_t*)(Al + (r + 8) * PADB + kb + 16);
            }
#pragma unroll
            for (int j = 0; j < 4; j++) {
                int n = wc + j * 8 + g;
                bh[j][0] = *(const uint32_t*)(Bh + n * PADB + kb);
                bh[j][1] = *(const uint32_t*)(Bh + n * PADB + kb + 16);
                bl[j][0] = *(const uint32_t*)(Bl + n * PADB + kb);
                bl[j][1] = *(const uint32_t*)(Bl + n * PADB + kb + 16);
            }
#pragma unroll
            for (int i = 0; i < 2; i++)
#pragma unroll
                for (int j = 0; j < 4; j++) {
                    mma16816(acc[i][j], ah[i], bh[j]);
                    mma16816(acc[i][j], al[i], bh[j]);
                    mma16816(acc[i][j], ah[i], bl[j]);
                }
        }
        __syncthreads();
    }

    const int colg = colbase + half * 128 + wc;
#pragma unroll
    for (int i = 0; i < 2; i++) {
        int r = row0 + wr + i * 16 + g;
#pragma unroll
        for (int j = 0; j < 4; j++) {
            int cgl = colg + j * 8 + tg * 2;
            float2 o0, o1;
            o0.x = fmaxf(acc[i][j][0], 0.f);
            o0.y = fmaxf(acc[i][j][1], 0.f);
            o1.x = fmaxf(acc[i][j][2], 0.f);
            o1.y = fmaxf(acc[i][j][3], 0.f);
            *(float2*)(out + (size_t)r * 256 + cgl) = o0;
            *(float2*)(out + (size_t)(r + 8) * 256 + cgl) = o1;
        }
    }
}

// ---------------- launch: two-stream DAG ----------------
extern "C" void kernel_launch(void* const* d_in, const int* in_sizes, int n_in,
                              void* d_out, int out_size) {
    const float* feat = (const float*)d_in[0];
    const float* ws0  = (const float*)d_in[1];
    const float* wn0  = (const float*)d_in[2];
    const float* ws1  = (const float*)d_in[3];
    const float* wn1  = (const float*)d_in[4];
    const int*   s0   = (const int*)d_in[5];
    const int*   s1   = (const int*)d_in[6];
    const int*   s2   = (const int*)d_in[7];
    float* out = (float*)d_out;

    float *pX0, *pY0, *pM1;
    cudaGetSymbolAddress((void**)&pX0, g_X0);
    cudaGetSymbolAddress((void**)&pY0, g_Y0);
    cudaGetSymbolAddress((void**)&pM1, g_M1);

    static cudaStream_t sB = nullptr;
    static cudaEvent_t evFork = nullptr, evJoin = nullptr;
    if (sB == nullptr) {
        cudaStreamCreateWithFlags(&sB, cudaStreamNonBlocking);
        cudaEventCreateWithFlags(&evFork, cudaEventDisableTiming);
        cudaEventCreateWithFlags(&evJoin, cudaEventDisableTiming);
    }

    const size_t smMMA = (size_t)(2 * 64 + 2 * 128) * PADB;   // 104448
    cudaFuncSetAttribute(mega_kernel,
                         cudaFuncAttributeMaxDynamicSharedMemorySize, (int)smMMA);
    cudaFuncSetAttribute(small_hmma_kernel,
                         cudaFuncAttributeMaxDynamicSharedMemorySize, (int)smMMA);

    // stream A (default): prep+zero -> mega (with in-kernel tail)
    prep_w_kernel<<<160, 256>>>(ws0, wn0, ws1, wn1);
    cudaEventRecord(evFork, 0);

    // stream B: gather0 -> l0 -> l1-self (independent of mega)
    cudaStreamWaitEvent(sB, evFork, 0);
    gather0_kernel<<<128, 256, 0, sB>>>(feat, s0, s1);
    small_hmma_kernel<<<dim3(16, 2), 256, smMMA, sB>>>(pX0, pX0, 128, 0, 16384, 128, 1, 0, pY0);
    small_hmma_kernel<<<dim3(16, 1), 256, smMMA, sB>>>(pY0, pY0, 0, 32768, 0, 256, 2, 0, out);
    cudaEventRecord(evJoin, sB);

    // stream A continues: mega computes Y1 contributions + tail in last CTAs
    mega_kernel<<<MEGA_BLOCKS, 256, smMMA>>>(feat, s1, s2, out);
    cudaStreamWaitEvent(0, evJoin, 0);
}

// round 16
// speedup vs baseline: 1.2725x; 1.2725x over previous
#include <cuda_runtime.h>
#include <cuda_bf16.h>
#include <cstdint>

#define NB   1024
#define NS1  25
#define NS2  10
#define DF   128
#define ROWS1 (NB * NS1)   // 25600
#define MEGA_BLOCKS (2 * (ROWS1 / 64))   // 800

// ---------------- scratch (no allocations allowed) ----------------
__device__ float g_X0[(size_t)NB * 256];
__device__ float g_Y0[(size_t)NB * 256];
__device__ float g_M1[(size_t)NB * 256];     // accumulated mean over s1 (atomic)
// W^T bf16 hi/lo: [ws0: 128n x 128k @0][wn0: @16384][ws1: 128n x 256k @32768][wn1: @65536]
__device__ __align__(16) __nv_bfloat16 g_WtH[98304];
__device__ __align__(16) __nv_bfloat16 g_WtL[98304];

// ---------------- helpers ----------------
__device__ __forceinline__ void split4(const float4& v, uint2& hi, uint2& lo) {
    float vv[4] = {v.x, v.y, v.z, v.w};
    uint32_t hp[2], lp[2];
#pragma unroll
    for (int q = 0; q < 2; q++) {
        __nv_bfloat16 h0 = __float2bfloat16(vv[2 * q]);
        __nv_bfloat16 h1 = __float2bfloat16(vv[2 * q + 1]);
        __nv_bfloat16 l0 = __float2bfloat16(vv[2 * q] - __bfloat162float(h0));
        __nv_bfloat16 l1 = __float2bfloat16(vv[2 * q + 1] - __bfloat162float(h1));
        hp[q] = ((uint32_t)__bfloat16_as_ushort(h1) << 16) | __bfloat16_as_ushort(h0);
        lp[q] = ((uint32_t)__bfloat16_as_ushort(l1) << 16) | __bfloat16_as_ushort(l0);
    }
    hi = make_uint2(hp[0], hp[1]);
    lo = make_uint2(lp[0], lp[1]);
}
__device__ __forceinline__ uint32_t smem_to_u32(const void* p) {
    uint32_t a;
    asm("{ .reg .u64 t; cvta.to.shared.u64 t, %1; cvt.u32.u64 %0, t; }"
        : "=r"(a) : "l"(p));
    return a;
}
#define CP_ASYNC16(dst_u32, src_ptr) \
    asm volatile("cp.async.cg.shared.global [%0], [%1], 16;" \
        :: "r"(dst_u32), "l"(src_ptr) : "memory")
#define CP_ASYNC_WAIT_ALL() \
    asm volatile("cp.async.commit_group;\ncp.async.wait_group 0;" ::: "memory")

__device__ __forceinline__ void mma16816(float* c, const uint32_t* a, const uint32_t* b) {
    asm volatile(
        "mma.sync.aligned.m16n8k16.row.col.f32.bf16.bf16.f32 "
        "{%0,%1,%2,%3}, {%4,%5,%6,%7}, {%8,%9}, {%0,%1,%2,%3};"
        : "+f"(c[0]), "+f"(c[1]), "+f"(c[2]), "+f"(c[3])
        : "r"(a[0]), "r"(a[1]), "r"(a[2]), "r"(a[3]), "r"(b[0]), "r"(b[1]));
}
__device__ __forceinline__ void f4add(float4& a, const float4& b) {
    a.x += b.x; a.y += b.y; a.z += b.z; a.w += b.w;
}
__device__ __forceinline__ float4 ldcs4(const float* p) {
    return __ldcs((const float4*)p);
}

// ---------------- weight tile transpose+split (device fn) ----------------
__device__ void prep_tile(const float* __restrict__ W, int K, int off, int tile) {
    __shared__ float t[32][33];
    int tr = (tile >> 2) * 32;
    int tc = (tile & 3) * 32;
    int tx = threadIdx.x & 31, ty = threadIdx.x >> 5;
#pragma unroll
    for (int p = 0; p < 32; p += 8)
        t[ty + p][tx] = W[(size_t)(tr + ty + p) * 128 + tc + tx];
    __syncthreads();
#pragma unroll
    for (int p = 0; p < 32; p += 8) {
        int n = tc + ty + p, k = tr + tx;
        float v = t[tx][ty + p];
        __nv_bfloat16 h = __float2bfloat16(v);
        __nv_bfloat16 l = __float2bfloat16(v - __bfloat162float(h));
        size_t o = (size_t)off + (size_t)n * K + k;
        g_WtH[o] = h;
        g_WtL[o] = l;
    }
}

// ---------------- prep0: w0 weights (32 blocks) + zero M1 (64 blocks) ----------------
__global__ void prep0_kernel(const float* __restrict__ w0s, const float* __restrict__ w0n) {
    int b = blockIdx.x;
    if (b >= 32) {
        int u = (b - 32) * 256 + threadIdx.x;     // 64 blocks * 256 = 16384 threads
        for (int i = u; i < 65536; i += 16384)
            ((float4*)g_M1)[i] = make_float4(0.f, 0.f, 0.f, 0.f);
        return;
    }
    if (b < 16) prep_tile(w0s, 128, 0, b);
    else        prep_tile(w0n, 128, 16384, b - 16);
}

// ---------------- prep1: w1 weights (64 blocks), runs on stream B ----------------
__global__ void prep1_kernel(const float* __restrict__ w1s, const float* __restrict__ w1n) {
    int b = blockIdx.x;
    if (b < 32) prep_tile(w1s, 256, 32768, b);
    else        prep_tile(w1n, 256, 65536, b - 32);
}

// ---------------- gather0: X0 = [h0 | mean_S1(h1)], MLP-batched ----------------
__global__ void gather0_kernel(const float* __restrict__ feat,
                               const int* __restrict__ s0,
                               const int* __restrict__ s1) {
    int warp = (blockIdx.x * blockDim.x + threadIdx.x) >> 5;
    int lane = threadIdx.x & 31;
    if (warp >= NB) return;
    int c = lane * 4;

    long iself = s0[warp];
    *(float4*)(g_X0 + (size_t)warp * 256 + c) =
        *(const float4*)(feat + iself * DF + c);

    const int* p = s1 + (size_t)warp * NS1;
    int idxs[NS1];
#pragma unroll
    for (int j = 0; j < NS1; j++) idxs[j] = p[j];

    float4 acc = make_float4(0.f, 0.f, 0.f, 0.f);
#pragma unroll
    for (int base = 0; base < 25; base += 5) {
        float4 v[5];
#pragma unroll
        for (int j = 0; j < 5; j++)
            v[j] = *(const float4*)(feat + (long)idxs[base + j] * DF + c);
        f4add(v[0], v[1]); f4add(v[2], v[3]); f4add(v[0], v[2]);
        f4add(v[0], v[4]); f4add(acc, v[0]);
    }
    const float s = 1.0f / NS1;
    acc.x *= s; acc.y *= s; acc.z *= s; acc.w *= s;
    *(float4*)(g_X0 + (size_t)warp * 256 + 128 + c) = acc;
}

// ---------------- mega: fused gather + HMMA bf16x3 + atomic mean into M1 ----------------
#define PADB 272   // smem row pitch in bytes

__global__ __launch_bounds__(256, 2)
void mega_kernel(const float* __restrict__ feat,
                 const int* __restrict__ s1,
                 const int* __restrict__ s2) {
    const int tid = threadIdx.x;
    const int wid = tid >> 5;
    const int lane = tid & 31;
    const int c = lane * 4;

    extern __shared__ char sb[];
    const uint32_t OFF_AH = 0;
    const uint32_t OFF_AL = 64 * PADB;
    const uint32_t OFF_BH = 2 * 64 * PADB;
    const uint32_t OFF_BL = OFF_BH + 128 * PADB;
    const uint32_t smb = smem_to_u32(sb);

    const int half = blockIdx.x & 1;
    const int row0 = (blockIdx.x >> 1) * 64;

    for (int idx = tid; idx < 2048; idx += 256) {
        int n = idx >> 4;
        int ch = (idx & 15) * 16;
        size_t gsrc = (size_t)half * 16384 + (size_t)n * 128;
        uint32_t dst = n * PADB + ch;
        CP_ASYNC16(smb + OFF_BH + dst, (const char*)(g_WtH + gsrc) + ch);
        CP_ASYNC16(smb + OFF_BL + dst, (const char*)(g_WtL + gsrc) + ch);
    }

    if (half == 0) {
        long idxs[8];
#pragma unroll
        for (int it = 0; it < 8; it++) idxs[it] = s1[row0 + wid + it * 8];
        float4 v[8];
#pragma unroll
        for (int it = 0; it < 8; it++)
            v[it] = *(const float4*)(feat + idxs[it] * DF + c);
#pragma unroll
        for (int it = 0; it < 8; it++) {
            const int r = wid + it * 8;
            uint2 h, l;
            split4(v[it], h, l);
            *(uint2*)(sb + OFF_AH + r * PADB + lane * 8) = h;
            *(uint2*)(sb + OFF_AL + r * PADB + lane * 8) = l;
        }
    } else {
#pragma unroll
        for (int it = 0; it < 8; it++) {
            const int r = wid + it * 8;
            const int gr = row0 + r;
            const int* p = s2 + (size_t)gr * NS2;
            int idxs[NS2];
#pragma unroll
            for (int j = 0; j < NS2; j++) idxs[j] = p[j];
            float4 v[NS2];
#pragma unroll
            for (int j = 0; j < NS2; j++)
                v[j] = ldcs4(feat + (long)idxs[j] * DF + c);   // touch-once: streaming
            f4add(v[0], v[1]); f4add(v[2], v[3]); f4add(v[4], v[5]);
            f4add(v[6], v[7]); f4add(v[8], v[9]);
            f4add(v[0], v[2]); f4add(v[4], v[6]);
            f4add(v[0], v[4]); f4add(v[0], v[8]);
            const float s = 1.0f / NS2;
            v[0].x *= s; v[0].y *= s; v[0].z *= s; v[0].w *= s;
            uint2 h, l;
            split4(v[0], h, l);
            *(uint2*)(sb + OFF_AH + r * PADB + lane * 8) = h;
            *(uint2*)(sb + OFF_AL + r * PADB + lane * 8) = l;
        }
    }
    CP_ASYNC_WAIT_ALL();
    __syncthreads();

    const char* Ah = sb + OFF_AH;
    const char* Al = sb + OFF_AL;
    const char* Bh = sb + OFF_BH;
    const char* Bl = sb + OFF_BL;

    const int g = lane >> 2;
    const int tg = lane & 3;
    const int wr = (wid >> 2) * 32;
    const int wc = (wid & 3) * 32;

    float acc[2][4][4];
#pragma unroll
    for (int i = 0; i < 2; i++)
#pragma unroll
        for (int j = 0; j < 4; j++)
#pragma unroll
            for (int q = 0; q < 4; q++) acc[i][j][q] = 0.f;

#pragma unroll
    for (int ks = 0; ks < 8; ks++) {
        const int kb = (ks * 16 + tg * 2) * 2;
        uint32_t ah[2][4], al[2][4], bh[4][2], bl[4][2];
#pragma unroll
        for (int i = 0; i < 2; i++) {
            int r = wr + i * 16 + g;
            ah[i][0] = *(const uint32_t*)(Ah + r * PADB + kb);
            ah[i][1] = *(const uint32_t*)(Ah + (r + 8) * PADB + kb);
            ah[i][2] = *(const uint32_t*)(Ah + r * PADB + kb + 16);
            ah[i][3] = *(const uint32_t*)(Ah + (r + 8) * PADB + kb + 16);
            al[i][0] = *(const uint32_t*)(Al + r * PADB + kb);
            al[i][1] = *(const uint32_t*)(Al + (r + 8) * PADB + kb);
            al[i][2] = *(const uint32_t*)(Al + r * PADB + kb + 16);
            al[i][3] = *(const uint32_t*)(Al + (r + 8) * PADB + kb + 16);
        }
#pragma unroll
        for (int j = 0; j < 4; j++) {
            int n = wc + j * 8 + g;
            bh[j][0] = *(const uint32_t*)(Bh + n * PADB + kb);
            bh[j][1] = *(const uint32_t*)(Bh + n * PADB + kb + 16);
            bl[j][0] = *(const uint32_t*)(Bl + n * PADB + kb);
            bl[j][1] = *(const uint32_t*)(Bl + n * PADB + kb + 16);
        }
#pragma unroll
        for (int i = 0; i < 2; i++)
#pragma unroll
            for (int j = 0; j < 4; j++) {
                mma16816(acc[i][j], ah[i], bh[j]);
                mma16816(acc[i][j], al[i], bh[j]);
                mma16816(acc[i][j], ah[i], bl[j]);
            }
    }

    const int colg = half * 128 + wc;
    const float inv25 = 1.0f / NS1;
#pragma unroll
    for (int i = 0; i < 2; i++) {
        int r0g = row0 + wr + i * 16 + g;
        int b0 = r0g / NS1;
        int b1 = (r0g + 8) / NS1;
#pragma unroll
        for (int j = 0; j < 4; j++) {
            int cgl = colg + j * 8 + tg * 2;
            atomicAdd(&g_M1[(size_t)b0 * 256 + cgl],     fmaxf(acc[i][j][0], 0.f) * inv25);
            atomicAdd(&g_M1[(size_t)b0 * 256 + cgl + 1], fmaxf(acc[i][j][1], 0.f) * inv25);
            atomicAdd(&g_M1[(size_t)b1 * 256 + cgl],     fmaxf(acc[i][j][2], 0.f) * inv25);
            atomicAdd(&g_M1[(size_t)b1 * 256 + cgl + 1], fmaxf(acc[i][j][3], 0.f) * inv25);
        }
    }
}

// ---------------- small HMMA GEMM (64x128 tiles) ----------------
__global__ __launch_bounds__(256, 2)
void small_hmma_kernel(const float* __restrict__ A0, const float* __restrict__ A1,
                       int acolmul, int woffbase, int woffstep, int kstride,
                       int kc_count, int colbase, float* __restrict__ out) {
    extern __shared__ char sb[];
    const uint32_t OFF_AH = 0;
    const uint32_t OFF_AL = 64 * PADB;
    const uint32_t OFF_BH = 2 * 64 * PADB;
    const uint32_t OFF_BL = OFF_BH + 128 * PADB;
    const uint32_t smb = smem_to_u32(sb);

    const int half = blockIdx.y;
    const int row0 = blockIdx.x * 64;
    const int tid = threadIdx.x;
    const int wid = tid >> 5;
    const int lane = tid & 31;
    const float* A = half ? A1 : A0;
    const int acol0 = acolmul * half;
    const int woff = woffbase + half * woffstep;

    const int g = lane >> 2;
    const int tg = lane & 3;
    const int wr = (wid >> 2) * 32;
    const int wc = (wid & 3) * 32;

    float acc[2][4][4];
#pragma unroll
    for (int i = 0; i < 2; i++)
#pragma unroll
        for (int j = 0; j < 4; j++)
#pragma unroll
            for (int q = 0; q < 4; q++) acc[i][j][q] = 0.f;

    for (int kc = 0; kc < kc_count; kc++) {
        const int koff = kc * 128;
        for (int idx = tid; idx < 2048; idx += 256) {
            int n = idx >> 4;
            int ch = (idx & 15) * 16;
            size_t gsrc = (size_t)woff + (size_t)n * kstride + koff;
            uint32_t dst = n * PADB + ch;
            CP_ASYNC16(smb + OFF_BH + dst, (const char*)(g_WtH + gsrc) + ch);
            CP_ASYNC16(smb + OFF_BL + dst, (const char*)(g_WtL + gsrc) + ch);
        }
        for (int idx = tid; idx < 2048; idx += 256) {
            int r = idx >> 5;
            int cc4 = (idx & 31) * 4;
            float4 v = *(const float4*)(A + (size_t)(row0 + r) * 256 + acol0 + koff + cc4);
            uint2 h, l;
            split4(v, h, l);
            *(uint2*)(sb + OFF_AH + r * PADB + cc4 * 2) = h;
            *(uint2*)(sb + OFF_AL + r * PADB + cc4 * 2) = l;
        }
        CP_ASYNC_WAIT_ALL();
        __syncthreads();

        const char* Ah = sb + OFF_AH;
        const char* Al = sb + OFF_AL;
        const char* Bh = sb + OFF_BH;
        const char* Bl = sb + OFF_BL;

#pragma unroll
        for (int ks = 0; ks < 8; ks++) {
            const int kb = (ks * 16 + tg * 2) * 2;
            uint32_t ah[2][4], al[2][4], bh[4][2], bl[4][2];
#pragma unroll
            for (int i = 0; i < 2; i++) {
                int r = wr + i * 16 + g;
                ah[i][0] = *(const uint32_t*)(Ah + r * PADB + kb);
                ah[i][1] = *(const uint32_t*)(Ah + (r + 8) * PADB + kb);
                ah[i][2] = *(const uint32_t*)(Ah + r * PADB + kb + 16);
                ah[i][3] = *(const uint32_t*)(Ah + (r + 8) * PADB + kb + 16);
                al[i][0] = *(const uint32_t*)(Al + r * PADB + kb);
                al[i][1] = *(const uint32_t*)(Al + (r + 8) * PADB + kb);
                al[i][2] = *(const uint32_t*)(Al + r * PADB + kb + 16);
                al[i][3] = *(const uint32_t*)(Al + (r + 8) * PADB + kb + 16);
            }
#pragma unroll
            for (int j = 0; j < 4; j++) {
                int n = wc + j * 8 + g;
                bh[j][0] = *(const uint32_t*)(Bh + n * PADB + kb);
                bh[j][1] = *(const uint32_t*)(Bh + n * PADB + kb + 16);
                bl[j][0] = *(const uint32_t*)(Bl + n * PADB + kb);
                bl[j][1] = *(const uint32_t*)(Bl + n * PADB + kb + 16);
            }
#pragma unroll
            for (int i = 0; i < 2; i++)
#pragma unroll
                for (int j = 0; j < 4; j++) {
                    mma16816(acc[i][j], ah[i], bh[j]);
                    mma16816(acc[i][j], al[i], bh[j]);
                    mma16816(acc[i][j], ah[i], bl[j]);
                }
        }
        __syncthreads();
    }

    const int colg = colbase + half * 128 + wc;
#pragma unroll
    for (int i = 0; i < 2; i++) {
        int r = row0 + wr + i * 16 + g;
#pragma unroll
        for (int j = 0; j < 4; j++) {
            int cgl = colg + j * 8 + tg * 2;
            float2 o0, o1;
            o0.x = fmaxf(acc[i][j][0], 0.f);
            o0.y = fmaxf(acc[i][j][1], 0.f);
            o1.x = fmaxf(acc[i][j][2], 0.f);
            o1.y = fmaxf(acc[i][j][3], 0.f);
            *(float2*)(out + (size_t)r * 256 + cgl) = o0;
            *(float2*)(out + (size_t)(r + 8) * 256 + cgl) = o1;
        }
    }
}

// ---------------- tail: out[:,128+n] = relu(M1 @ Wn1), 64x64 tiles, grid (16,2) ----------------
__global__ __launch_bounds__(256, 2)
void tail_neigh_kernel(float* __restrict__ out) {
    extern __shared__ char sb[];
    const uint32_t OFF_AH = 0;
    const uint32_t OFF_AL = 64 * PADB;
    const uint32_t OFF_BH = 2 * 64 * PADB;
    const uint32_t OFF_BL = 3 * 64 * PADB;
    const uint32_t smb = smem_to_u32(sb);

    const int row0 = blockIdx.x * 64;
    const int n0 = blockIdx.y * 64;
    const int tid = threadIdx.x;
    const int wid = tid >> 5;
    const int lane = tid & 31;

    const int g = lane >> 2;
    const int tg = lane & 3;
    const int wr = (wid >> 1) * 16;
    const int wc = (wid & 1) * 32;

    float acc[4][4];
#pragma unroll
    for (int j = 0; j < 4; j++)
#pragma unroll
        for (int q = 0; q < 4; q++) acc[j][q] = 0.f;

    for (int kc = 0; kc < 2; kc++) {
        const int koff = kc * 128;
        for (int idx = tid; idx < 1024; idx += 256) {
            int n = idx >> 4;
            int ch = (idx & 15) * 16;
            size_t gsrc = 65536 + (size_t)(n0 + n) * 256 + koff;
            uint32_t dst = n * PADB + ch;
            CP_ASYNC16(smb + OFF_BH + dst, (const char*)(g_WtH + gsrc) + ch);
            CP_ASYNC16(smb + OFF_BL + dst, (const char*)(g_WtL + gsrc) + ch);
        }
        for (int idx = tid; idx < 2048; idx += 256) {
            int r = idx >> 5;
            int cc4 = (idx & 31) * 4;
            float4 v = *(const float4*)(g_M1 + (size_t)(row0 + r) * 256 + koff + cc4);
            uint2 h, l;
            split4(v, h, l);
            *(uint2*)(sb + OFF_AH + r * PADB + cc4 * 2) = h;
            *(uint2*)(sb + OFF_AL + r * PADB + cc4 * 2) = l;
        }
        CP_ASYNC_WAIT_ALL();
        __syncthreads();

        const char* Ah = sb + OFF_AH;
        const char* Al = sb + OFF_AL;
        const char* Bh = sb + OFF_BH;
        const char* Bl = sb + OFF_BL;

#pragma unroll
        for (int ks = 0; ks < 8; ks++) {
            const int kb = (ks * 16 + tg * 2) * 2;
            uint32_t ah[4], al[4], bh[4][2], bl[4][2];
            int r = wr + g;
            ah[0] = *(const uint32_t*)(Ah + r * PADB + kb);
            ah[1] = *(const uint32_t*)(Ah + (r + 8) * PADB + kb);
            ah[2] = *(const uint32_t*)(Ah + r * PADB + kb + 16);
            ah[3] = *(const uint32_t*)(Ah + (r + 8) * PADB + kb + 16);
            al[0] = *(const uint32_t*)(Al + r * PADB + kb);
            al[1] = *(const uint32_t*)(Al + (r + 8) * PADB + kb);
            al[2] = *(const uint32_t*)(Al + r * PADB + kb + 16);
            al[3] = *(const uint32_t*)(Al + (r + 8) * PADB + kb + 16);
#pragma unroll
            for (int j = 0; j < 4; j++) {
                int n = wc + j * 8 + g;
                bh[j][0] = *(const uint32_t*)(Bh + n * PADB + kb);
                bh[j][1] = *(const uint32_t*)(Bh + n * PADB + kb + 16);
                bl[j][0] = *(const uint32_t*)(Bl + n * PADB + kb);
                bl[j][1] = *(const uint32_t*)(Bl + n * PADB + kb + 16);
            }
#pragma unroll
            for (int j = 0; j < 4; j++) {
                mma16816(acc[j], ah, bh[j]);
                mma16816(acc[j], al, bh[j]);
                mma16816(acc[j], ah, bl[j]);
            }
        }
        __syncthreads();
    }

    const int colg = 128 + n0 + wc;
    int r = row0 + wr + g;
#pragma unroll
    for (int j = 0; j < 4; j++) {
        int cgl = colg + j * 8 + tg * 2;
        float2 o0, o1;
        o0.x = fmaxf(acc[j][0], 0.f);
        o0.y = fmaxf(acc[j][1], 0.f);
        o1.x = fmaxf(acc[j][2], 0.f);
        o1.y = fmaxf(acc[j][3], 0.f);
        *(float2*)(out + (size_t)r * 256 + cgl) = o0;
        *(float2*)(out + (size_t)(r + 8) * 256 + cgl) = o1;
    }
}

// ---------------- launch: two-stream DAG with split prep ----------------
extern "C" void kernel_launch(void* const* d_in, const int* in_sizes, int n_in,
                              void* d_out, int out_size) {
    const float* feat = (const float*)d_in[0];
    const float* ws0  = (const float*)d_in[1];
    const float* wn0  = (const float*)d_in[2];
    const float* ws1  = (const float*)d_in[3];
    const float* wn1  = (const float*)d_in[4];
    const int*   s0   = (const int*)d_in[5];
    const int*   s1   = (const int*)d_in[6];
    const int*   s2   = (const int*)d_in[7];
    float* out = (float*)d_out;

    float *pX0, *pY0, *pM1;
    cudaGetSymbolAddress((void**)&pX0, g_X0);
    cudaGetSymbolAddress((void**)&pY0, g_Y0);
    cudaGetSymbolAddress((void**)&pM1, g_M1);

    static cudaStream_t sB = nullptr;
    static cudaEvent_t evStart = nullptr, evFork = nullptr, evW1 = nullptr, evJoin = nullptr;
    if (sB == nullptr) {
        cudaStreamCreateWithFlags(&sB, cudaStreamNonBlocking);
        cudaEventCreateWithFlags(&evStart, cudaEventDisableTiming);
        cudaEventCreateWithFlags(&evFork, cudaEventDisableTiming);
        cudaEventCreateWithFlags(&evW1, cudaEventDisableTiming);
        cudaEventCreateWithFlags(&evJoin, cudaEventDisableTiming);
    }

    const size_t smMMA = (size_t)(2 * 64 + 2 * 128) * PADB;   // 104448
    const size_t smTail = (size_t)(4 * 64) * PADB;            //  69632
    cudaFuncSetAttribute(mega_kernel,
                         cudaFuncAttributeMaxDynamicSharedMemorySize, (int)smMMA);
    cudaFuncSetAttribute(small_hmma_kernel,
                         cudaFuncAttributeMaxDynamicSharedMemorySize, (int)smMMA);
    cudaFuncSetAttribute(tail_neigh_kernel,
                         cudaFuncAttributeMaxDynamicSharedMemorySize, (int)smTail);

    // stream A: prep0 (w0 + zero M1) -> mega -> tail-neigh
    cudaEventRecord(evStart, 0);
    prep0_kernel<<<96, 256>>>(ws0, wn0);
    cudaEventRecord(evFork, 0);

    // stream B: prep1 (w1) || gather0 -> l0 -> l1-self
    cudaStreamWaitEvent(sB, evStart, 0);
    prep1_kernel<<<64, 256, 0, sB>>>(ws1, wn1);
    cudaEventRecord(evW1, sB);
    cudaStreamWaitEvent(sB, evFork, 0);
    gather0_kernel<<<128, 256, 0, sB>>>(feat, s0, s1);
    small_hmma_kernel<<<dim3(16, 2), 256, smMMA, sB>>>(pX0, pX0, 128, 0, 16384, 128, 1, 0, pY0);
    small_hmma_kernel<<<dim3(16, 1), 256, smMMA, sB>>>(pY0, pY0, 0, 32768, 0, 256, 2, 0, out);
    cudaEventRecord(evJoin, sB);

    // stream A continues
    mega_kernel<<<MEGA_BLOCKS, 256, smMMA>>>(feat, s1, s2);
    cudaStreamWaitEvent(0, evW1, 0);
    tail_neigh_kernel<<<dim3(16, 2), 256, smTail>>>(out);
    cudaStreamWaitEvent(0, evJoin, 0);
}

// round 17
// speedup vs baseline: 1.3534x; 1.0636x over previous
#include <cuda_runtime.h>
#include <cuda_bf16.h>
#include <cstdint>

#define NB   1024
#define NS1  25
#define NS2  10
#define DF   128
#define ROWS1 (NB * NS1)   // 25600
#define MEGA_BLOCKS (2 * (ROWS1 / 64))   // 800

// ---------------- scratch (no allocations allowed) ----------------
__device__ float g_X0[(size_t)NB * 256];
__device__ float g_Y0[(size_t)NB * 256];
__device__ float g_M1[(size_t)NB * 256];     // accumulated mean over s1 (atomic)
// W^T bf16 hi/lo: [ws0: 128n x 128k @0][wn0: @16384][ws1: 128n x 256k @32768][wn1: @65536]
__device__ __align__(16) __nv_bfloat16 g_WtH[98304];
__device__ __align__(16) __nv_bfloat16 g_WtL[98304];

// ---------------- helpers ----------------
__device__ __forceinline__ void split4(const float4& v, uint2& hi, uint2& lo) {
    float vv[4] = {v.x, v.y, v.z, v.w};
    uint32_t hp[2], lp[2];
#pragma unroll
    for (int q = 0; q < 2; q++) {
        __nv_bfloat16 h0 = __float2bfloat16(vv[2 * q]);
        __nv_bfloat16 h1 = __float2bfloat16(vv[2 * q + 1]);
        __nv_bfloat16 l0 = __float2bfloat16(vv[2 * q] - __bfloat162float(h0));
        __nv_bfloat16 l1 = __float2bfloat16(vv[2 * q + 1] - __bfloat162float(h1));
        hp[q] = ((uint32_t)__bfloat16_as_ushort(h1) << 16) | __bfloat16_as_ushort(h0);
        lp[q] = ((uint32_t)__bfloat16_as_ushort(l1) << 16) | __bfloat16_as_ushort(l0);
    }
    hi = make_uint2(hp[0], hp[1]);
    lo = make_uint2(lp[0], lp[1]);
}
__device__ __forceinline__ uint32_t smem_to_u32(const void* p) {
    uint32_t a;
    asm("{ .reg .u64 t; cvta.to.shared.u64 t, %1; cvt.u32.u64 %0, t; }"
        : "=r"(a) : "l"(p));
    return a;
}
#define CP_ASYNC16(dst_u32, src_ptr) \
    asm volatile("cp.async.cg.shared.global [%0], [%1], 16;" \
        :: "r"(dst_u32), "l"(src_ptr) : "memory")
#define CP_ASYNC_WAIT_ALL() \
    asm volatile("cp.async.commit_group;\ncp.async.wait_group 0;" ::: "memory")

__device__ __forceinline__ void mma16816(float* c, const uint32_t* a, const uint32_t* b) {
    asm volatile(
        "mma.sync.aligned.m16n8k16.row.col.f32.bf16.bf16.f32 "
        "{%0,%1,%2,%3}, {%4,%5,%6,%7}, {%8,%9}, {%0,%1,%2,%3};"
        : "+f"(c[0]), "+f"(c[1]), "+f"(c[2]), "+f"(c[3])
        : "r"(a[0]), "r"(a[1]), "r"(a[2]), "r"(a[3]), "r"(b[0]), "r"(b[1]));
}
__device__ __forceinline__ void f4add(float4& a, const float4& b) {
    a.x += b.x; a.y += b.y; a.z += b.z; a.w += b.w;
}
__device__ __forceinline__ float4 ldcs4(const float* p) {
    return __ldcs((const float4*)p);
}

// ---------------- prep: weights; blocks >=96 zero M1 ----------------
__global__ void prep_w_kernel(const float* __restrict__ w0s, const float* __restrict__ w0n,
                              const float* __restrict__ w1s, const float* __restrict__ w1n) {
    int b = blockIdx.x;
    if (b >= 96) {
        int u = (b - 96) * 256 + threadIdx.x;     // 64 blocks * 256 = 16384 threads
        for (int i = u; i < 65536; i += 16384)
            ((float4*)g_M1)[i] = make_float4(0.f, 0.f, 0.f, 0.f);
        return;
    }
    __shared__ float t[32][33];
    const float* W; int K, off, tile;
    if (b < 16)      { W = w0s; K = 128; off = 0;     tile = b; }
    else if (b < 32) { W = w0n; K = 128; off = 16384; tile = b - 16; }
    else if (b < 64) { W = w1s; K = 256; off = 32768; tile = b - 32; }
    else             { W = w1n; K = 256; off = 65536; tile = b - 64; }
    int tr = (tile >> 2) * 32;
    int tc = (tile & 3) * 32;
    int tx = threadIdx.x & 31, ty = threadIdx.x >> 5;
#pragma unroll
    for (int p = 0; p < 32; p += 8)
        t[ty + p][tx] = W[(size_t)(tr + ty + p) * 128 + tc + tx];
    __syncthreads();
#pragma unroll
    for (int p = 0; p < 32; p += 8) {
        int n = tc + ty + p, k = tr + tx;
        float v = t[tx][ty + p];
        __nv_bfloat16 h = __float2bfloat16(v);
        __nv_bfloat16 l = __float2bfloat16(v - __bfloat162float(h));
        size_t o = (size_t)off + (size_t)n * K + k;
        g_WtH[o] = h;
        g_WtL[o] = l;
    }
}

// ---------------- gather0: X0 = [h0 | mean_S1(h1)], MLP-batched ----------------
__global__ void gather0_kernel(const float* __restrict__ feat,
                               const int* __restrict__ s0,
                               const int* __restrict__ s1) {
    int warp = (blockIdx.x * blockDim.x + threadIdx.x) >> 5;
    int lane = threadIdx.x & 31;
    if (warp >= NB) return;
    int c = lane * 4;

    long iself = s0[warp];
    *(float4*)(g_X0 + (size_t)warp * 256 + c) =
        *(const float4*)(feat + iself * DF + c);

    const int* p = s1 + (size_t)warp * NS1;
    int idxs[NS1];
#pragma unroll
    for (int j = 0; j < NS1; j++) idxs[j] = p[j];

    float4 acc = make_float4(0.f, 0.f, 0.f, 0.f);
#pragma unroll
    for (int base = 0; base < 25; base += 5) {
        float4 v[5];
#pragma unroll
        for (int j = 0; j < 5; j++)
            v[j] = *(const float4*)(feat + (long)idxs[base + j] * DF + c);
        f4add(v[0], v[1]); f4add(v[2], v[3]); f4add(v[0], v[2]);
        f4add(v[0], v[4]); f4add(acc, v[0]);
    }
    const float s = 1.0f / NS1;
    acc.x *= s; acc.y *= s; acc.z *= s; acc.w *= s;
    *(float4*)(g_X0 + (size_t)warp * 256 + 128 + c) = acc;
}

// ---------------- mega: fused gather + HMMA bf16x3 + atomic mean into M1 ----------------
#define PADB 272   // smem row pitch in bytes

__global__ __launch_bounds__(256, 2)
void mega_kernel(const float* __restrict__ feat,
                 const int* __restrict__ s1,
                 const int* __restrict__ s2) {
    const int tid = threadIdx.x;
    const int wid = tid >> 5;
    const int lane = tid & 31;
    const int c = lane * 4;

    extern __shared__ char sb[];
    const uint32_t OFF_AH = 0;
    const uint32_t OFF_AL = 64 * PADB;
    const uint32_t OFF_BH = 2 * 64 * PADB;
    const uint32_t OFF_BL = OFF_BH + 128 * PADB;
    const uint32_t smb = smem_to_u32(sb);

    const int half = blockIdx.x & 1;
    const int row0 = (blockIdx.x >> 1) * 64;

    for (int idx = tid; idx < 2048; idx += 256) {
        int n = idx >> 4;
        int ch = (idx & 15) * 16;
        size_t gsrc = (size_t)half * 16384 + (size_t)n * 128;
        uint32_t dst = n * PADB + ch;
        CP_ASYNC16(smb + OFF_BH + dst, (const char*)(g_WtH + gsrc) + ch);
        CP_ASYNC16(smb + OFF_BL + dst, (const char*)(g_WtL + gsrc) + ch);
    }

    if (half == 0) {
        long idxs[8];
#pragma unroll
        for (int it = 0; it < 8; it++) idxs[it] = s1[row0 + wid + it * 8];
        float4 v[8];
#pragma unroll
        for (int it = 0; it < 8; it++)
            v[it] = *(const float4*)(feat + idxs[it] * DF + c);
#pragma unroll
        for (int it = 0; it < 8; it++) {
            const int r = wid + it * 8;
            uint2 h, l;
            split4(v[it], h, l);
            *(uint2*)(sb + OFF_AH + r * PADB + lane * 8) = h;
            *(uint2*)(sb + OFF_AL + r * PADB + lane * 8) = l;
        }
    } else {
#pragma unroll
        for (int it = 0; it < 8; it++) {
            const int r = wid + it * 8;
            const int gr = row0 + r;
            const int* p = s2 + (size_t)gr * NS2;
            int idxs[NS2];
#pragma unroll
            for (int j = 0; j < NS2; j++) idxs[j] = p[j];
            float4 v[NS2];
#pragma unroll
            for (int j = 0; j < NS2; j++)
                v[j] = ldcs4(feat + (long)idxs[j] * DF + c);   // touch-once: streaming
            f4add(v[0], v[1]); f4add(v[2], v[3]); f4add(v[4], v[5]);
            f4add(v[6], v[7]); f4add(v[8], v[9]);
            f4add(v[0], v[2]); f4add(v[4], v[6]);
            f4add(v[0], v[4]); f4add(v[0], v[8]);
            const float s = 1.0f / NS2;
            v[0].x *= s; v[0].y *= s; v[0].z *= s; v[0].w *= s;
            uint2 h, l;
            split4(v[0], h, l);
            *(uint2*)(sb + OFF_AH + r * PADB + lane * 8) = h;
            *(uint2*)(sb + OFF_AL + r * PADB + lane * 8) = l;
        }
    }
    CP_ASYNC_WAIT_ALL();
    __syncthreads();

    const char* Ah = sb + OFF_AH;
    const char* Al = sb + OFF_AL;
    const char* Bh = sb + OFF_BH;
    const char* Bl = sb + OFF_BL;

    const int g = lane >> 2;
    const int tg = lane & 3;
    const int wr = (wid >> 2) * 32;
    const int wc = (wid & 3) * 32;

    float acc[2][4][4];
#pragma unroll
    for (int i = 0; i < 2; i++)
#pragma unroll
        for (int j = 0; j < 4; j++)
#pragma unroll
            for (int q = 0; q < 4; q++) acc[i][j][q] = 0.f;

#pragma unroll
    for (int ks = 0; ks < 8; ks++) {
        const int kb = (ks * 16 + tg * 2) * 2;
        uint32_t ah[2][4], al[2][4], bh[4][2], bl[4][2];
#pragma unroll
        for (int i = 0; i < 2; i++) {
            int r = wr + i * 16 + g;
            ah[i][0] = *(const uint32_t*)(Ah + r * PADB + kb);
            ah[i][1] = *(const uint32_t*)(Ah + (r + 8) * PADB + kb);
            ah[i][2] = *(const uint32_t*)(Ah + r * PADB + kb + 16);
            ah[i][3] = *(const uint32_t*)(Ah + (r + 8) * PADB + kb + 16);
            al[i][0] = *(const uint32_t*)(Al + r * PADB + kb);
            al[i][1] = *(const uint32_t*)(Al + (r + 8) * PADB + kb);
            al[i][2] = *(const uint32_t*)(Al + r * PADB + kb + 16);
            al[i][3] = *(const uint32_t*)(Al + (r + 8) * PADB + kb + 16);
        }
#pragma unroll
        for (int j = 0; j < 4; j++) {
            int n = wc + j * 8 + g;
            bh[j][0] = *(const uint32_t*)(Bh + n * PADB + kb);
            bh[j][1] = *(const uint32_t*)(Bh + n * PADB + kb + 16);
            bl[j][0] = *(const uint32_t*)(Bl + n * PADB + kb);
            bl[j][1] = *(const uint32_t*)(Bl + n * PADB + kb + 16);
        }
#pragma unroll
        for (int i = 0; i < 2; i++)
#pragma unroll
            for (int j = 0; j < 4; j++) {
                mma16816(acc[i][j], ah[i], bh[j]);
                mma16816(acc[i][j], al[i], bh[j]);
                mma16816(acc[i][j], ah[i], bl[j]);
            }
    }

    const int colg = half * 128 + wc;
    const float inv25 = 1.0f / NS1;
#pragma unroll
    for (int i = 0; i < 2; i++) {
        int r0g = row0 + wr + i * 16 + g;
        int b0 = r0g / NS1;
        int b1 = (r0g + 8) / NS1;
#pragma unroll
        for (int j = 0; j < 4; j++) {
            int cgl = colg + j * 8 + tg * 2;
            atomicAdd(&g_M1[(size_t)b0 * 256 + cgl],     fmaxf(acc[i][j][0], 0.f) * inv25);
            atomicAdd(&g_M1[(size_t)b0 * 256 + cgl + 1], fmaxf(acc[i][j][1], 0.f) * inv25);
            atomicAdd(&g_M1[(size_t)b1 * 256 + cgl],     fmaxf(acc[i][j][2], 0.f) * inv25);
            atomicAdd(&g_M1[(size_t)b1 * 256 + cgl + 1], fmaxf(acc[i][j][3], 0.f) * inv25);
        }
    }
}

// ---------------- small HMMA GEMM (64x128 tiles) ----------------
__global__ __launch_bounds__(256, 2)
void small_hmma_kernel(const float* __restrict__ A0, const float* __restrict__ A1,
                       int acolmul, int woffbase, int woffstep, int kstride,
                       int kc_count, int colbase, float* __restrict__ out) {
    extern __shared__ char sb[];
    const uint32_t OFF_AH = 0;
    const uint32_t OFF_AL = 64 * PADB;
    const uint32_t OFF_BH = 2 * 64 * PADB;
    const uint32_t OFF_BL = OFF_BH + 128 * PADB;
    const uint32_t smb = smem_to_u32(sb);

    const int half = blockIdx.y;
    const int row0 = blockIdx.x * 64;
    const int tid = threadIdx.x;
    const int wid = tid >> 5;
    const int lane = tid & 31;
    const float* A = half ? A1 : A0;
    const int acol0 = acolmul * half;
    const int woff = woffbase + half * woffstep;

    const int g = lane >> 2;
    const int tg = lane & 3;
    const int wr = (wid >> 2) * 32;
    const int wc = (wid & 3) * 32;

    float acc[2][4][4];
#pragma unroll
    for (int i = 0; i < 2; i++)
#pragma unroll
        for (int j = 0; j < 4; j++)
#pragma unroll
            for (int q = 0; q < 4; q++) acc[i][j][q] = 0.f;

    for (int kc = 0; kc < kc_count; kc++) {
        const int koff = kc * 128;
        for (int idx = tid; idx < 2048; idx += 256) {
            int n = idx >> 4;
            int ch = (idx & 15) * 16;
            size_t gsrc = (size_t)woff + (size_t)n * kstride + koff;
            uint32_t dst = n * PADB + ch;
            CP_ASYNC16(smb + OFF_BH + dst, (const char*)(g_WtH + gsrc) + ch);
            CP_ASYNC16(smb + OFF_BL + dst, (const char*)(g_WtL + gsrc) + ch);
        }
        for (int idx = tid; idx < 2048; idx += 256) {
            int r = idx >> 5;
            int cc4 = (idx & 31) * 4;
            float4 v = *(const float4*)(A + (size_t)(row0 + r) * 256 + acol0 + koff + cc4);
            uint2 h, l;
            split4(v, h, l);
            *(uint2*)(sb + OFF_AH + r * PADB + cc4 * 2) = h;
            *(uint2*)(sb + OFF_AL + r * PADB + cc4 * 2) = l;
        }
        CP_ASYNC_WAIT_ALL();
        __syncthreads();

        const char* Ah = sb + OFF_AH;
        const char* Al = sb + OFF_AL;
        const char* Bh = sb + OFF_BH;
        const char* Bl = sb + OFF_BL;

#pragma unroll
        for (int ks = 0; ks < 8; ks++) {
            const int kb = (ks * 16 + tg * 2) * 2;
            uint32_t ah[2][4], al[2][4], bh[4][2], bl[4][2];
#pragma unroll
            for (int i = 0; i < 2; i++) {
                int r = wr + i * 16 + g;
                ah[i][0] = *(const uint32_t*)(Ah + r * PADB + kb);
                ah[i][1] = *(const uint32_t*)(Ah + (r + 8) * PADB + kb);
                ah[i][2] = *(const uint32_t*)(Ah + r * PADB + kb + 16);
                ah[i][3] = *(const uint32_t*)(Ah + (r + 8) * PADB + kb + 16);
                al[i][0] = *(const uint32_t*)(Al + r * PADB + kb);
                al[i][1] = *(const uint32_t*)(Al + (r + 8) * PADB + kb);
                al[i][2] = *(const uint32_t*)(Al + r * PADB + kb + 16);
                al[i][3] = *(const uint32_t*)(Al + (r + 8) * PADB + kb + 16);
            }
#pragma unroll
            for (int j = 0; j < 4; j++) {
                int n = wc + j * 8 + g;
                bh[j][0] = *(const uint32_t*)(Bh + n * PADB + kb);
                bh[j][1] = *(const uint32_t*)(Bh + n * PADB + kb + 16);
                bl[j][0] = *(const uint32_t*)(Bl + n * PADB + kb);
                bl[j][1] = *(const uint32_t*)(Bl + n * PADB + kb + 16);
            }
#pragma unroll
            for (int i = 0; i < 2; i++)
#pragma unroll
                for (int j = 0; j < 4; j++) {
                    mma16816(acc[i][j], ah[i], bh[j]);
                    mma16816(acc[i][j], al[i], bh[j]);
                    mma16816(acc[i][j], ah[i], bl[j]);
                }
        }
        __syncthreads();
    }

    const int colg = colbase + half * 128 + wc;
#pragma unroll
    for (int i = 0; i < 2; i++) {
        int r = row0 + wr + i * 16 + g;
#pragma unroll
        for (int j = 0; j < 4; j++) {
            int cgl = colg + j * 8 + tg * 2;
            float2 o0, o1;
            o0.x = fmaxf(acc[i][j][0], 0.f);
            o0.y = fmaxf(acc[i][j][1], 0.f);
            o1.x = fmaxf(acc[i][j][2], 0.f);
            o1.y = fmaxf(acc[i][j][3], 0.f);
            *(float2*)(out + (size_t)r * 256 + cgl) = o0;
            *(float2*)(out + (size_t)(r + 8) * 256 + cgl) = o1;
        }
    }
}

// ---------------- tail: out[:,128+n] = relu(M1 @ Wn1), 32x64 tiles, grid (32,2) ----------------
__global__ __launch_bounds__(256, 2)
void tail_neigh_kernel(float* __restrict__ out) {
    extern __shared__ char sb[];
    const uint32_t OFF_AH = 0;
    const uint32_t OFF_AL = 32 * PADB;
    const uint32_t OFF_BH = 2 * 32 * PADB;
    const uint32_t OFF_BL = OFF_BH + 64 * PADB;
    const uint32_t smb = smem_to_u32(sb);

    const int row0 = blockIdx.x * 32;
    const int n0 = blockIdx.y * 64;
    const int tid = threadIdx.x;
    const int wid = tid >> 5;
    const int lane = tid & 31;

    const int g = lane >> 2;
    const int tg = lane & 3;
    const int wr = (wid >> 2) * 16;   // 2 row groups of 16
    const int wc = (wid & 3) * 16;    // 4 col groups of 16

    float acc[2][4];
#pragma unroll
    for (int j = 0; j < 2; j++)
#pragma unroll
        for (int q = 0; q < 4; q++) acc[j][q] = 0.f;

    for (int kc = 0; kc < 2; kc++) {
        const int koff = kc * 128;
        // stage B: 64 n-rows x 128 k bf16 hi/lo (Wn1 at 65536, kstride 256)
        for (int idx = tid; idx < 1024; idx += 256) {
            int n = idx >> 4;
            int ch = (idx & 15) * 16;
            size_t gsrc = 65536 + (size_t)(n0 + n) * 256 + koff;
            uint32_t dst = n * PADB + ch;
            CP_ASYNC16(smb + OFF_BH + dst, (const char*)(g_WtH + gsrc) + ch);
            CP_ASYNC16(smb + OFF_BL + dst, (const char*)(g_WtL + gsrc) + ch);
        }
        // stage A: 32 rows x 128 fp32 -> bf16 hi/lo
        for (int idx = tid; idx < 1024; idx += 256) {
            int r = idx >> 5;
            int cc4 = (idx & 31) * 4;
            float4 v = *(const float4*)(g_M1 + (size_t)(row0 + r) * 256 + koff + cc4);
            uint2 h, l;
            split4(v, h, l);
            *(uint2*)(sb + OFF_AH + r * PADB + cc4 * 2) = h;
            *(uint2*)(sb + OFF_AL + r * PADB + cc4 * 2) = l;
        }
        CP_ASYNC_WAIT_ALL();
        __syncthreads();

        const char* Ah = sb + OFF_AH;
        const char* Al = sb + OFF_AL;
        const char* Bh = sb + OFF_BH;
        const char* Bl = sb + OFF_BL;

#pragma unroll
        for (int ks = 0; ks < 8; ks++) {
            const int kb = (ks * 16 + tg * 2) * 2;
            uint32_t ah[4], al[4], bh[2][2], bl[2][2];
            int r = wr + g;
            ah[0] = *(const uint32_t*)(Ah + r * PADB + kb);
            ah[1] = *(const uint32_t*)(Ah + (r + 8) * PADB + kb);
            ah[2] = *(const uint32_t*)(Ah + r * PADB + kb + 16);
            ah[3] = *(const uint32_t*)(Ah + (r + 8) * PADB + kb + 16);
            al[0] = *(const uint32_t*)(Al + r * PADB + kb);
            al[1] = *(const uint32_t*)(Al + (r + 8) * PADB + kb);
            al[2] = *(const uint32_t*)(Al + r * PADB + kb + 16);
            al[3] = *(const uint32_t*)(Al + (r + 8) * PADB + kb + 16);
#pragma unroll
            for (int j = 0; j < 2; j++) {
                int n = wc + j * 8 + g;
                bh[j][0] = *(const uint32_t*)(Bh + n * PADB + kb);
                bh[j][1] = *(const uint32_t*)(Bh + n * PADB + kb + 16);
                bl[j][0] = *(const uint32_t*)(Bl + n * PADB + kb);
                bl[j][1] = *(const uint32_t*)(Bl + n * PADB + kb + 16);
            }
#pragma unroll
            for (int j = 0; j < 2; j++) {
                mma16816(acc[j], ah, bh[j]);
                mma16816(acc[j], al, bh[j]);
                mma16816(acc[j], ah, bl[j]);
            }
        }
        __syncthreads();
    }

    const int colg = 128 + n0 + wc;
    int r = row0 + wr + g;
#pragma unroll
    for (int j = 0; j < 2; j++) {
        int cgl = colg + j * 8 + tg * 2;
        float2 o0, o1;
        o0.x = fmaxf(acc[j][0], 0.f);
        o0.y = fmaxf(acc[j][1], 0.f);
        o1.x = fmaxf(acc[j][2], 0.f);
        o1.y = fmaxf(acc[j][3], 0.f);
        *(float2*)(out + (size_t)r * 256 + cgl) = o0;
        *(float2*)(out + (size_t)(r + 8) * 256 + cgl) = o1;
    }
}

// ---------------- launch: two-stream DAG (R14 structure) ----------------
extern "C" void kernel_launch(void* const* d_in, const int* in_sizes, int n_in,
                              void* d_out, int out_size) {
    const float* feat = (const float*)d_in[0];
    const float* ws0  = (const float*)d_in[1];
    const float* wn0  = (const float*)d_in[2];
    const float* ws1  = (const float*)d_in[3];
    const float* wn1  = (const float*)d_in[4];
    const int*   s0   = (const int*)d_in[5];
    const int*   s1   = (const int*)d_in[6];
    const int*   s2   = (const int*)d_in[7];
    float* out = (float*)d_out;

    float *pX0, *pY0, *pM1;
    cudaGetSymbolAddress((void**)&pX0, g_X0);
    cudaGetSymbolAddress((void**)&pY0, g_Y0);
    cudaGetSymbolAddress((void**)&pM1, g_M1);

    static cudaStream_t sB = nullptr;
    static cudaEvent_t evFork = nullptr, evJoin = nullptr;
    if (sB == nullptr) {
        cudaStreamCreateWithFlags(&sB, cudaStreamNonBlocking);
        cudaEventCreateWithFlags(&evFork, cudaEventDisableTiming);
        cudaEventCreateWithFlags(&evJoin, cudaEventDisableTiming);
    }

    const size_t smMMA = (size_t)(2 * 64 + 2 * 128) * PADB;   // 104448
    const size_t smTail = (size_t)(2 * 32 + 2 * 64) * PADB;   //  52224
    cudaFuncSetAttribute(mega_kernel,
                         cudaFuncAttributeMaxDynamicSharedMemorySize, (int)smMMA);
    cudaFuncSetAttribute(small_hmma_kernel,
                         cudaFuncAttributeMaxDynamicSharedMemorySize, (int)smMMA);
    cudaFuncSetAttribute(tail_neigh_kernel,
                         cudaFuncAttributeMaxDynamicSharedMemorySize, (int)smTail);

    // stream A: prep+zero -> mega -> tail-neigh
    prep_w_kernel<<<160, 256>>>(ws0, wn0, ws1, wn1);
    cudaEventRecord(evFork, 0);

    // stream B: gather0 -> l0 -> l1-self (independent of mega)
    cudaStreamWaitEvent(sB, evFork, 0);
    gather0_kernel<<<128, 256, 0, sB>>>(feat, s0, s1);
    small_hmma_kernel<<<dim3(16, 2), 256, smMMA, sB>>>(pX0, pX0, 128, 0, 16384, 128, 1, 0, pY0);
    small_hmma_kernel<<<dim3(16, 1), 256, smMMA, sB>>>(pY0, pY0, 0, 32768, 0, 256, 2, 0, out);
    cudaEventRecord(evJoin, sB);

    // stream A continues
    mega_kernel<<<MEGA_BLOCKS, 256, smMMA>>>(feat, s1, s2);
    tail_neigh_kernel<<<dim3(32, 2), 256, smTail>>>(out);
    cudaStreamWaitEvent(0, evJoin, 0);
}